// round 4
// baseline (speedup 1.0000x reference)
#include <cuda_runtime.h>

// GCN_18760417149681 — fully linear GraphSAGE collapse, v3.
// out[m] = inv[m]*SB[m] + xs[m] + (deg[m]>0)*CB + C2
// where SB = Σ_{edges into m} (t[src] + xg[src]),  t = SA/max(deg,1),
// SA = Σ xp[src], and xp/xg/xs are dots of x[node] with precomputed 64-vecs.

#define NMAX 100000
#define NFEAT 64
#define NHID 128

// ---- precomputed small vectors / consts ----
__device__ __align__(16) float g_P[NFEAT];
__device__ __align__(16) float g_G[NFEAT];
__device__ __align__(16) float g_S[NFEAT];
__device__ float g_C[2];   // [0]=cb (gated by deg>0), [1]=c2 (always)
__device__ int   g_is64;   // 1 if edge_idx is int64, else int32

// ---- per-node scratch (kept small for L2/L1 residency of random gathers) ----
__device__ float  g_XP[NMAX];                  // 400KB  (gathered in scatter1)
__device__ float  g_XG[NMAX];                  // 400KB
__device__ float  g_XS[NMAX];                  // 400KB
__device__ __align__(8) float2 g_ACC[NMAX];    // (SA, deg) 800KB atomic target
__device__ float  g_Z[NMAX];                   // 400KB  (gathered in scatter2)
__device__ float  g_SB[NMAX];                  // 400KB atomic target

// ===================== prep: collapse weights + dtype sniff =====================
__global__ void k_prep(const float* __restrict__ Wl1, const float* __restrict__ Wr1,
                       const float* __restrict__ b1,
                       const float* __restrict__ Wl2, const float* __restrict__ Wr2,
                       const float* __restrict__ b2,
                       const float* __restrict__ Wfc1, const float* __restrict__ bfc1,
                       const float* __restrict__ Wfc2, const float* __restrict__ bfc2,
                       const int* __restrict__ ei32, int E)
{
    __shared__ float sw[NHID], su[NHID], sv[NHID];
    int t = threadIdx.x;  // 0..127

    // dtype sniff: int64 little-endian small indices => odd 32-bit words all 0
    if (t == 0) {
        int odd_nonzero = 0;
        for (int k = 0; k < 64; k++) {
            long long pos = 1 + (long long)k * ((2LL * E - 2) / 64);
            pos |= 1;
            if (ei32[pos] != 0) odd_nonzero++;
        }
        g_is64 = (odd_nonzero == 0) ? 1 : 0;
    }

    // w = Wfc1 @ Wfc2
    float acc = 0.f;
    #pragma unroll
    for (int c = 0; c < 32; c++) acc += Wfc1[t * 32 + c] * Wfc2[c];
    sw[t] = acc;
    __syncthreads();

    // u = Wl2 @ w, v = Wr2 @ w
    float au = 0.f, av = 0.f;
    #pragma unroll 4
    for (int j = 0; j < NHID; j++) {
        float wv = sw[j];
        au += Wl2[t * NHID + j] * wv;
        av += Wr2[t * NHID + j] * wv;
    }
    su[t] = au; sv[t] = av;
    __syncthreads();

    // p = Wl1@u, g = Wr1@u + Wl1@v, s = Wr1@v
    if (t < NFEAT) {
        float p = 0.f, g = 0.f, s = 0.f;
        #pragma unroll 4
        for (int j = 0; j < NHID; j++) {
            float wl = Wl1[t * NHID + j];
            float wr = Wr1[t * NHID + j];
            float uj = su[j], vj = sv[j];
            p += wl * uj;
            g += wr * uj + wl * vj;
            s += wr * vj;
        }
        g_P[t] = p; g_G[t] = g; g_S[t] = s;
    }

    if (t == 0) {
        float cb = 0.f, c2 = 0.f;
        for (int j = 0; j < NHID; j++) {
            cb += b1[j] * su[j];
            c2 += b1[j] * sv[j] + b2[j] * sw[j];
        }
        for (int c = 0; c < 32; c++) c2 += bfc1[c] * Wfc2[c];
        c2 += bfc2[0];
        g_C[0] = cb; g_C[1] = c2;
    }
}

// ===================== pass A: 3 dots per node + zero accumulators =====================
// half-warp (16 lanes) per node; lane covers one float4 (4 feats).
__global__ void __launch_bounds__(256) k_passA(const float* __restrict__ x, int n)
{
    int node = (blockIdx.x * blockDim.x + threadIdx.x) >> 4;
    int lane = threadIdx.x & 15;
    if (node >= n) return;

    float4 xv = __ldg(((const float4*)x) + (long long)node * 16 + lane);
    float4 pv = ((const float4*)g_P)[lane];
    float4 gv = ((const float4*)g_G)[lane];
    float4 sv = ((const float4*)g_S)[lane];

    float xp = xv.x * pv.x + xv.y * pv.y + xv.z * pv.z + xv.w * pv.w;
    float xg = xv.x * gv.x + xv.y * gv.y + xv.z * gv.z + xv.w * gv.w;
    float xs = xv.x * sv.x + xv.y * sv.y + xv.z * sv.z + xv.w * sv.w;

    #pragma unroll
    for (int off = 8; off; off >>= 1) {
        xp += __shfl_xor_sync(0xffffffffu, xp, off);
        xg += __shfl_xor_sync(0xffffffffu, xg, off);
        xs += __shfl_xor_sync(0xffffffffu, xs, off);
    }
    if (lane == 0) {
        g_XP[node]  = xp;
        g_XG[node]  = xg;
        g_XS[node]  = xs;
        g_ACC[node] = make_float2(0.f, 0.f);
        g_SB[node]  = 0.f;
    }
}

// ===================== scatter pass 1: float2 atomic (SA, deg), 2 edges/thread ==========
__global__ void __launch_bounds__(256) k_scatter1(const int* __restrict__ ei32, int E)
{
    int base = (blockIdx.x * blockDim.x + threadIdx.x) * 2;
    if (base >= E) return;
    bool two = (base + 1 < E);
    int s0, d0, s1 = 0, d1 = 0;
    if (g_is64) {
        const longlong2* s2 = (const longlong2*)((const long long*)ei32 + base);
        const longlong2* d2 = (const longlong2*)((const long long*)ei32 + E + base);
        longlong2 ss = __ldg(s2);
        longlong2 dd = __ldg(d2);
        s0 = (int)ss.x; s1 = (int)ss.y; d0 = (int)dd.x; d1 = (int)dd.y;
    } else {
        int2 ss = __ldg((const int2*)(ei32 + base));
        int2 dd = __ldg((const int2*)(ei32 + E + base));
        s0 = ss.x; s1 = ss.y; d0 = dd.x; d1 = dd.y;
    }
    float xp0 = __ldg(&g_XP[s0]);
    float xp1 = two ? __ldg(&g_XP[s1]) : 0.f;
    atomicAdd(&g_ACC[d0], make_float2(xp0, 1.0f));
    if (two) atomicAdd(&g_ACC[d1], make_float2(xp1, 1.0f));
}

// ===================== pass T: Z[i] = SA/max(deg,1) + xg[i] =====================
__global__ void __launch_bounds__(256) k_passT(int n)
{
    int i = blockIdx.x * blockDim.x + threadIdx.x;
    if (i < n) {
        float2 a = g_ACC[i];
        g_Z[i] = a.x * __frcp_rn(fmaxf(a.y, 1.0f)) + g_XG[i];
    }
}

// ===================== scatter pass 2: SB += Z[src], 2 edges/thread =====================
__global__ void __launch_bounds__(256) k_scatter2(const int* __restrict__ ei32, int E)
{
    int base = (blockIdx.x * blockDim.x + threadIdx.x) * 2;
    if (base >= E) return;
    bool two = (base + 1 < E);
    int s0, d0, s1 = 0, d1 = 0;
    if (g_is64) {
        const longlong2* s2 = (const longlong2*)((const long long*)ei32 + base);
        const longlong2* d2 = (const longlong2*)((const long long*)ei32 + E + base);
        longlong2 ss = __ldg(s2);
        longlong2 dd = __ldg(d2);
        s0 = (int)ss.x; s1 = (int)ss.y; d0 = (int)dd.x; d1 = (int)dd.y;
    } else {
        int2 ss = __ldg((const int2*)(ei32 + base));
        int2 dd = __ldg((const int2*)(ei32 + E + base));
        s0 = ss.x; s1 = ss.y; d0 = dd.x; d1 = dd.y;
    }
    float z0 = __ldg(&g_Z[s0]);
    float z1 = two ? __ldg(&g_Z[s1]) : 0.f;
    atomicAdd(&g_SB[d0], z0);
    if (two) atomicAdd(&g_SB[d1], z1);
}

// ===================== final =====================
__global__ void __launch_bounds__(256) k_final(float* __restrict__ out, int n)
{
    int i = blockIdx.x * blockDim.x + threadIdx.x;
    if (i < n) {
        float cb = g_C[0], c2 = g_C[1];
        float2 a = g_ACC[i];
        float inv = __frcp_rn(fmaxf(a.y, 1.0f));
        float res = inv * g_SB[i] + g_XS[i] + c2;
        if (a.y > 0.0f) res += cb;
        out[i] = res;
    }
}

// ===================== launch =====================
extern "C" void kernel_launch(void* const* d_in, const int* in_sizes, int n_in,
                              void* d_out, int out_size)
{
    const float* x    = (const float*)d_in[0];
    const int*   ei32 = (const int*)d_in[1];   // int32 or int64 — sniffed on device
    // d_in[2] = edge_weight (unused by the reference)
    const float* Wl1  = (const float*)d_in[3];
    const float* Wr1  = (const float*)d_in[4];
    const float* b1   = (const float*)d_in[5];
    const float* Wl2  = (const float*)d_in[6];
    const float* Wr2  = (const float*)d_in[7];
    const float* b2   = (const float*)d_in[8];
    const float* Wfc1 = (const float*)d_in[9];
    const float* bfc1 = (const float*)d_in[10];
    const float* Wfc2 = (const float*)d_in[11];
    const float* bfc2 = (const float*)d_in[12];
    float* out = (float*)d_out;

    int N = in_sizes[0] / NFEAT;   // 100000
    int E = in_sizes[2];           // 1600000 (edge_weight element count)

    k_prep<<<1, 128>>>(Wl1, Wr1, b1, Wl2, Wr2, b2, Wfc1, bfc1, Wfc2, bfc2, ei32, E);

    // half-warp per node -> 16 nodes per 256-thread block
    k_passA<<<(N + 15) / 16, 256>>>(x, N);

    int tb = 256;
    int eb = (E + tb * 2 - 1) / (tb * 2);   // 2 edges per thread
    k_scatter1<<<eb, tb>>>(ei32, E);
    k_passT<<<(N + tb - 1) / tb, tb>>>(N);
    k_scatter2<<<eb, tb>>>(ei32, E);
    k_final<<<(N + tb - 1) / tb, tb>>>(out, N);
}